// round 14
// baseline (speedup 1.0000x reference)
#include <cuda_runtime.h>
#include <cuda_fp16.h>

// ---------------- problem constants ----------------
// N=32768, M=8192, D=128, H=128, NH=2 -> hidden 256, HD=64
#define NMAX 32768
#define MMAX 8192
#define EMAX 49152
#define TMAX 294912
#define PMAX (TMAX + NMAX)

// node table cols: [0:256) S(+bsi+bti+bbi) | [256:512) T | [512:768) T2(+bse+bte) | [768:896) M(+bmi)
#define NCC 896
// edge table cols: [0:256) B | [256:512) S | [512:640) M | [640:768) Me(+bme)
#define ECC 768

// ---------------- scratch ----------------
__device__ __half g_node[(size_t)NMAX * NCC];
__device__ __half g_edge[(size_t)MMAX * ECC];
__device__ float  g_accO[(size_t)NMAX * 256];   // [N][256]: intra 0-127, inter 128-255
__device__ __half g_Wn[128 * NCC];
__device__ __half g_We[128 * ECC];
__device__ __half g_Wo[256 * 128];
__device__ float  g_bn[NCC];
__device__ float  g_be[ECC];
__device__ float  g_bo[128];
__device__ float  g_denomI[NMAX * 2];
__device__ float  g_denomE[NMAX * 2];
// CSR: pair -> bridging edges
__device__ int    g_cnt[PMAX];
__device__ int    g_off[PMAX];
__device__ int    g_head[PMAX];
__device__ int    g_csr[TMAX];
__device__ int    g_partial[1024];

// ---------------- helpers ----------------
__device__ __forceinline__ float rcp_approx(float x) {
    float r;
    asm("rcp.approx.f32 %0, %1;" : "=f"(r) : "f"(x));
    return r;
}
// Branchless exact-gelu via Abramowitz-Stegun 7.1.26 (|erf err| <= 1.5e-7, all z>=0).
__device__ __forceinline__ float gelu_fast(float x) {
    float z = fabsf(x) * 0.70710678118654752f;
    float t = rcp_approx(fmaf(0.3275911f, z, 1.0f));
    float p = 1.061405429f;
    p = fmaf(p, t, -1.453152027f);
    p = fmaf(p, t, 1.421413741f);
    p = fmaf(p, t, -0.284496736f);
    p = fmaf(p, t, 0.254829592f);
    p = p * t;
    float ez = __expf(-z * z);
    float erfz = fmaf(-p, ez, 1.0f);         // erf(|x|/sqrt2) in [0,1)
    float r = copysignf(erfz, x);
    float hx = 0.5f * x;
    return fmaf(hx, r, hx);
}
__device__ __forceinline__ void red4(float* addr, float a, float b, float c, float d) {
    asm volatile("red.global.add.v4.f32 [%0], {%1,%2,%3,%4};"
                 :: "l"(addr), "f"(a), "f"(b), "f"(c), "f"(d) : "memory");
}
__device__ __forceinline__ void load_h8(const __half* p, float* f) {
    uint4 r = *(const uint4*)p;
    float2 v;
    v = __half22float2(*(__half2*)&r.x); f[0] = v.x; f[1] = v.y;
    v = __half22float2(*(__half2*)&r.y); f[2] = v.x; f[3] = v.y;
    v = __half22float2(*(__half2*)&r.z); f[4] = v.x; f[5] = v.y;
    v = __half22float2(*(__half2*)&r.w); f[6] = v.x; f[7] = v.y;
}
__device__ __forceinline__ void load_h4(const __half* p, float* f) {
    uint2 r = *(const uint2*)p;
    float2 v;
    v = __half22float2(*(__half2*)&r.x); f[0] = v.x; f[1] = v.y;
    v = __half22float2(*(__half2*)&r.y); f[2] = v.x; f[3] = v.y;
}

// ---------------- weight/bias packing + scratch zeroing ----------------
__global__ void pack_weights(const float* __restrict__ Wsi, const float* __restrict__ Wti,
                             const float* __restrict__ Wte, const float* __restrict__ Wmi,
                             const float* __restrict__ Wbi, const float* __restrict__ Wse,
                             const float* __restrict__ Wme,
                             const float* __restrict__ Woi, const float* __restrict__ Woe,
                             const float* __restrict__ bsi, const float* __restrict__ bti,
                             const float* __restrict__ bbi, const float* __restrict__ bse,
                             const float* __restrict__ bte, const float* __restrict__ bmi,
                             const float* __restrict__ bme, const float* __restrict__ boi,
                             const float* __restrict__ boe, int N, int P) {
    int i = blockIdx.x * blockDim.x + threadIdx.x;
    if (i < 128 * NCC) {
        int r = i / NCC, c = i % NCC;
        float v;
        if (c < 256) v = Wsi[r * 256 + c];
        else if (c < 512) v = Wti[r * 256 + (c - 256)];
        else if (c < 768) v = Wte[r * 256 + (c - 512)];
        else v = Wmi[r * 128 + (c - 768)];            // Wmi top half
        g_Wn[i] = __float2half(v);
    }
    if (i < 128 * ECC) {
        int r = i / ECC, c = i % ECC;
        float v;
        if (c < 256) v = Wbi[r * 256 + c];
        else if (c < 512) v = Wse[r * 256 + (c - 256)];
        else if (c < 640) v = Wmi[(128 + r) * 128 + (c - 512)];  // Wmi bottom half
        else v = Wme[r * 128 + (c - 640)];
        g_We[i] = __float2half(v);
    }
    if (i < 256 * 128) {
        int r = i / 128, c = i % 128;
        g_Wo[i] = __float2half((r < 128) ? Woi[r * 128 + c] : Woe[(r - 128) * 128 + c]);
    }
    if (i < NCC) {
        float v;
        if (i < 256) v = bsi[i] + bti[i] + bbi[i];
        else if (i < 512) v = 0.f;
        else if (i < 768) v = bse[i - 512] + bte[i - 512];
        else v = bmi[i - 768];
        g_bn[i] = v;
    }
    if (i < ECC) g_be[i] = (i >= 640) ? bme[i - 640] : 0.f;
    if (i < 128) g_bo[i] = boi[i] + boe[i];
    // zero softmax denominators + CSR counters (replaces 3 memsets)
    if (i < N * 2) { g_denomI[i] = 0.f; g_denomE[i] = 0.f; }
    if (i < P) g_cnt[i] = 0;
}

// ---------------- fp16 tensor-core GEMM, CTA tile 128x128, K-looped ---------
// Optional dI/dE: per-row softmax denominators folded into A staging
// (k<128 -> dI[row*2 + k/64], else dE[row*2 + k/64 - 2]; den<=0 -> 0).
#define AS_W 68
#define WP_W 136
#define GEMM_SMEM ((128 * AS_W + 64 * WP_W) * 4)

template <bool HALF_OUT>
__global__ void gemm_fp16_t(const float* __restrict__ A, const __half* __restrict__ W,
                            const float* __restrict__ bias, void* __restrict__ Cv,
                            int KK, int CC,
                            const float* __restrict__ dI, const float* __restrict__ dE) {
    extern __shared__ unsigned sh[];
    unsigned* As = sh;                 // 128*68 words
    unsigned* Wp = sh + 128 * AS_W;    // 64*136 words
    const int tid = threadIdx.x;
    const int lane = tid & 31;
    const int warp = tid >> 5;
    const int wm = warp & 3;           // 4 warps x 32 rows
    const int wn = warp >> 2;          // 2 warps x 64 cols
    const long r0 = (long)blockIdx.y * 128;
    const int  c0 = blockIdx.x * 128;
    const int gid = lane >> 2;
    const int tig = lane & 3;

    float c[2][8][4];
#pragma unroll
    for (int mt = 0; mt < 2; mt++)
#pragma unroll
        for (int nt = 0; nt < 8; nt++)
#pragma unroll
            for (int q = 0; q < 4; q++) c[mt][nt][q] = 0.f;

    for (int kb = 0; kb < KK; kb += 128) {
        if (kb) __syncthreads();
#pragma unroll
        for (int i = 0; i < 16; i++) {
            int idx = tid + i * 256;       // over [128][32 float4]
            int row = idx >> 5;
            int c4 = idx & 31;
            float4 v = *(const float4*)(A + (r0 + row) * KK + kb + c4 * 4);
            if (dI) {
                int kblk = (kb + c4 * 4) >> 6;     // 0..3, float4 never crosses a 64-block
                float den = (kblk < 2) ? dI[(r0 + row) * 2 + kblk]
                                       : dE[(r0 + row) * 2 + kblk - 2];
                float s = (den > 0.f) ? 1.0f / den : 0.f;
                v.x *= s; v.y *= s; v.z *= s; v.w *= s;
            }
            unsigned w0, w1;
            *(__half2*)&w0 = __floats2half2_rn(v.x, v.y);
            *(__half2*)&w1 = __floats2half2_rn(v.z, v.w);
            *(uint2*)(As + row * AS_W + c4 * 2) = make_uint2(w0, w1);
        }
#pragma unroll
        for (int i = 0; i < 4; i++) {
            int idx = tid + i * 256;       // over [64 kk][16 col-groups of 8]
            int kk = idx >> 4;
            int cg = idx & 15;
            const __half* we = W + (long)(kb + 2 * kk) * CC + c0 + cg * 8;
            uint4 e = *(const uint4*)we;
            uint4 o = *(const uint4*)(we + CC);
            const unsigned short* eh = (const unsigned short*)&e;
            const unsigned short* oh = (const unsigned short*)&o;
            unsigned out[8];
#pragma unroll
            for (int j = 0; j < 8; j++)
                out[j] = (unsigned)eh[j] | ((unsigned)oh[j] << 16);
            unsigned* dst = Wp + kk * WP_W + cg * 8;
            *(uint4*)dst = make_uint4(out[0], out[1], out[2], out[3]);
            *(uint4*)(dst + 4) = make_uint4(out[4], out[5], out[6], out[7]);
        }
        __syncthreads();

        const int arow = wm * 32 + gid;
        const int bcol = wn * 64 + gid;
#pragma unroll
        for (int step = 0; step < 8; step++) {
            int kw0 = step * 8;
            unsigned a[2][4], b[8][2];
#pragma unroll
            for (int mt = 0; mt < 2; mt++) {
                const unsigned* ap = As + (arow + mt * 16) * AS_W + kw0 + tig;
                a[mt][0] = ap[0];
                a[mt][1] = ap[8 * AS_W];
                a[mt][2] = ap[4];
                a[mt][3] = ap[8 * AS_W + 4];
            }
#pragma unroll
            for (int nt = 0; nt < 8; nt++) {
                b[nt][0] = Wp[(kw0 + tig) * WP_W + bcol + nt * 8];
                b[nt][1] = Wp[(kw0 + tig + 4) * WP_W + bcol + nt * 8];
            }
#pragma unroll
            for (int mt = 0; mt < 2; mt++)
#pragma unroll
                for (int nt = 0; nt < 8; nt++)
                    asm volatile(
                        "mma.sync.aligned.m16n8k16.row.col.f32.f16.f16.f32 "
                        "{%0,%1,%2,%3}, {%4,%5,%6,%7}, {%8,%9}, {%0,%1,%2,%3};"
                        : "+f"(c[mt][nt][0]), "+f"(c[mt][nt][1]),
                          "+f"(c[mt][nt][2]), "+f"(c[mt][nt][3])
                        : "r"(a[mt][0]), "r"(a[mt][1]), "r"(a[mt][2]), "r"(a[mt][3]),
                          "r"(b[nt][0]), "r"(b[nt][1]));
        }
    }

#pragma unroll
    for (int mt = 0; mt < 2; mt++) {
        long r = r0 + wm * 32 + mt * 16 + gid;
#pragma unroll
        for (int nt = 0; nt < 8; nt++) {
            int col = c0 + wn * 64 + nt * 8 + 2 * tig;
            float2 bv = bias ? *(const float2*)(bias + col) : make_float2(0.f, 0.f);
            float x0 = c[mt][nt][0] + bv.x, y0 = c[mt][nt][1] + bv.y;
            float x1 = c[mt][nt][2] + bv.x, y1 = c[mt][nt][3] + bv.y;
            if (HALF_OUT) {
                __half* C = (__half*)Cv;
                *(__half2*)(C + r * CC + col) = __floats2half2_rn(x0, y0);
                *(__half2*)(C + (r + 8) * CC + col) = __floats2half2_rn(x1, y1);
            } else {
                float* C = (float*)Cv;
                *(float2*)(C + r * CC + col) = make_float2(x0, y0);
                *(float2*)(C + (r + 8) * CC + col) = make_float2(x1, y1);
            }
        }
    }
}

// ---------------- CSR build: pair -> bridging edge list ---------------------
__global__ void csr_hist(const int* __restrict__ tri_pair, int T) {
    int i = blockIdx.x * blockDim.x + threadIdx.x;
    if (i < T) atomicAdd(&g_cnt[tri_pair[i]], 1);
}

__global__ void csr_scan_block(int P) {
    __shared__ int wsum[32];
    int tid = threadIdx.x;
    int base = blockIdx.x * 4096 + tid * 4;
    int v[4], s = 0;
#pragma unroll
    for (int q = 0; q < 4; q++) {
        v[q] = (base + q < P) ? g_cnt[base + q] : 0;
        s += v[q];
    }
    int lane = tid & 31, wid = tid >> 5;
    int x = s;
#pragma unroll
    for (int o = 1; o < 32; o <<= 1) {
        int y = __shfl_up_sync(0xffffffffu, x, o);
        if (lane >= o) x += y;
    }
    if (lane == 31) wsum[wid] = x;
    __syncthreads();
    if (wid == 0) {
        int w = wsum[lane];
#pragma unroll
        for (int o = 1; o < 32; o <<= 1) {
            int y = __shfl_up_sync(0xffffffffu, w, o);
            if (lane >= o) w += y;
        }
        wsum[lane] = w;
    }
    __syncthreads();
    int excl = x - s + (wid > 0 ? wsum[wid - 1] : 0);
    int run = excl;
#pragma unroll
    for (int q = 0; q < 4; q++) {
        if (base + q < P) g_off[base + q] = run;
        run += v[q];
    }
    if (tid == 1023) g_partial[blockIdx.x] = wsum[31];
}

__global__ void csr_scan_partials(int nb) {
    __shared__ int wsum[32];
    int tid = threadIdx.x;  // 1024
    int v = (tid < nb) ? g_partial[tid] : 0;
    int lane = tid & 31, wid = tid >> 5;
    int x = v;
#pragma unroll
    for (int o = 1; o < 32; o <<= 1) {
        int y = __shfl_up_sync(0xffffffffu, x, o);
        if (lane >= o) x += y;
    }
    if (lane == 31) wsum[wid] = x;
    __syncthreads();
    if (wid == 0) {
        int w = wsum[lane];
#pragma unroll
        for (int o = 1; o < 32; o <<= 1) {
            int y = __shfl_up_sync(0xffffffffu, w, o);
            if (lane >= o) w += y;
        }
        wsum[lane] = w;
    }
    __syncthreads();
    int excl = x - v + (wid > 0 ? wsum[wid - 1] : 0);
    if (tid < nb) g_partial[tid] = excl;
}

__global__ void csr_add_offsets(int P) {
    int i = blockIdx.x * blockDim.x + threadIdx.x;
    if (i < P) {
        int o = g_off[i] + g_partial[i >> 12];
        g_off[i] = o;
        g_head[i] = o;
    }
}

__global__ void csr_fill(const int* __restrict__ tri_pair,
                         const int* __restrict__ tri_edge, int T) {
    int i = blockIdx.x * blockDim.x + threadIdx.x;
    if (i < T) {
        int pos = atomicAdd(&g_head[tri_pair[i]], 1);
        g_csr[pos] = tri_edge[i];
    }
}

// ---------------- merged one-pass attention (intra + inter) -----------------
// warp id < P  -> intra pair, else inter incidence (id - P).
// NO launch_bounds: ~45+ live floats need >64 regs; capping causes spills (R13).
__global__ void attn_onepass(const int* __restrict__ pair_src, const int* __restrict__ pair_tgt,
                             const float* __restrict__ pair_cnt, const float* __restrict__ ai,
                             int P,
                             const int* __restrict__ inc_edge, const int* __restrict__ inc_node,
                             const float* __restrict__ ae, int E) {
    int w = (int)(((long)blockIdx.x * blockDim.x + threadIdx.x) >> 5);
    int lane = threadIdx.x & 31;

    if (w < P) {
        int s = pair_src[w], t = pair_tgt[w];
        float inv = 1.0f / pair_cnt[w];
        int deg = g_cnt[w];
        int off = g_off[w];

        float u[8], tv[8], m[4];
        load_h8(g_node + (size_t)s * NCC + lane * 8, u);            // S row (+biases)
        load_h8(g_node + (size_t)t * NCC + 256 + lane * 8, tv);     // T row
        load_h4(g_node + (size_t)s * NCC + 768 + lane * 4, m);      // M row (+bmi)
        float ab[8] = {0.f, 0.f, 0.f, 0.f, 0.f, 0.f, 0.f, 0.f};
        float am[4] = {0.f, 0.f, 0.f, 0.f};
        for (int j = 0; j < deg; j++) {
            int e = __ldg(&g_csr[off + j]);
            float bv[8], mv[4];
            load_h8(g_edge + (size_t)e * ECC + lane * 8, bv);       // B row
            load_h4(g_edge + (size_t)e * ECC + 512 + lane * 4, mv); // M row
#pragma unroll
            for (int q = 0; q < 8; q++) ab[q] += bv[q];
#pragma unroll
            for (int q = 0; q < 4; q++) am[q] += mv[q];
        }
        float4 a0 = *(const float4*)(ai + lane * 8);
        float4 a1 = *(const float4*)(ai + lane * 8 + 4);
        float av[8] = {a0.x, a0.y, a0.z, a0.w, a1.x, a1.y, a1.z, a1.w};
        float partial = 0.f;
#pragma unroll
        for (int q = 0; q < 8; q++)
            partial += gelu_fast(u[q] + tv[q] + ab[q] * inv) * av[q];
#pragma unroll
        for (int o = 8; o; o >>= 1) partial += __shfl_down_sync(0xffffffffu, partial, o);
        float l0 = __shfl_sync(0xffffffffu, partial, 0);
        float l1 = __shfl_sync(0xffffffffu, partial, 16);
        float e0 = __expf(l0), e1 = __expf(l1);
        if (lane == 0) {
            atomicAdd(&g_denomI[t * 2], e0);
            atomicAdd(&g_denomI[t * 2 + 1], e1);
        }
        float exh = (lane >> 4) ? e1 : e0;
        red4(g_accO + (size_t)t * 256 + lane * 4,
             exh * (m[0] + am[0] * inv), exh * (m[1] + am[1] * inv),
             exh * (m[2] + am[2] * inv), exh * (m[3] + am[3] * inv));
    } else if (w < P + E) {
        int i = w - P;
        int e = inc_edge[i], n = inc_node[i];
        float u[8], tv[8], m[4];
        load_h8(g_edge + (size_t)e * ECC + 256 + lane * 8, u);      // S(e) row
        load_h8(g_node + (size_t)n * NCC + 512 + lane * 8, tv);     // T2 row (+biases)
        load_h4(g_edge + (size_t)e * ECC + 640 + lane * 4, m);      // Me row (+bme)
        float4 a0 = *(const float4*)(ae + lane * 8);
        float4 a1 = *(const float4*)(ae + lane * 8 + 4);
        float av[8] = {a0.x, a0.y, a0.z, a0.w, a1.x, a1.y, a1.z, a1.w};
        float partial = 0.f;
#pragma unroll
        for (int q = 0; q < 8; q++)
            partial += gelu_fast(u[q] + tv[q]) * av[q];
#pragma unroll
        for (int o = 8; o; o >>= 1) partial += __shfl_down_sync(0xffffffffu, partial, o);
        float l0 = __shfl_sync(0xffffffffu, partial, 0);
        float l1 = __shfl_sync(0xffffffffu, partial, 16);
        float e0 = __expf(l0), e1 = __expf(l1);
        if (lane == 0) {
            atomicAdd(&g_denomE[n * 2], e0);
            atomicAdd(&g_denomE[n * 2 + 1], e1);
        }
        float exh = (lane >> 4) ? e1 : e0;
        red4(g_accO + (size_t)n * 256 + 128 + lane * 4,
             exh * m[0], exh * m[1], exh * m[2], exh * m[3]);
    }
}

// ---------------- launch ----------------
extern "C" void kernel_launch(void* const* d_in, const int* in_sizes, int n_in,
                              void* d_out, int out_size) {
    const float* node_feat = (const float*)d_in[0];
    const float* edge_feat = (const float*)d_in[1];
    const int*   inc_node  = (const int*)d_in[2];
    const int*   inc_edge  = (const int*)d_in[3];
    const int*   pair_src  = (const int*)d_in[4];
    const int*   pair_tgt  = (const int*)d_in[5];
    const float* pair_cnt  = (const float*)d_in[6];
    const int*   tri_pair  = (const int*)d_in[7];
    const int*   tri_edge  = (const int*)d_in[8];
    const float* Wsi = (const float*)d_in[9];
    const float* bsi = (const float*)d_in[10];
    const float* Wti = (const float*)d_in[11];
    const float* bti = (const float*)d_in[12];
    const float* Wbi = (const float*)d_in[13];
    const float* bbi = (const float*)d_in[14];
    const float* ai  = (const float*)d_in[15];
    const float* Wmi = (const float*)d_in[16];
    const float* bmi = (const float*)d_in[17];
    const float* Woi = (const float*)d_in[18];
    const float* boi = (const float*)d_in[19];
    const float* Wse = (const float*)d_in[20];
    const float* bse = (const float*)d_in[21];
    const float* Wte = (const float*)d_in[22];
    const float* bte = (const float*)d_in[23];
    const float* ae  = (const float*)d_in[24];
    const float* Wme = (const float*)d_in[25];
    const float* bme = (const float*)d_in[26];
    const float* Woe = (const float*)d_in[27];
    const float* boe = (const float*)d_in[28];

    const int N = in_sizes[0] / 128;
    const int M = in_sizes[1] / 128;
    const int E = in_sizes[2];
    const int P = in_sizes[4];
    const int T = in_sizes[7];
    if (N > NMAX || M > MMAX || E > EMAX || P > PMAX || T > TMAX) return;

    void *pNode, *pEdge, *pAccO, *pWn, *pWe, *pWo, *pBn, *pBe, *pBo, *pDenI, *pDenE;
    cudaGetSymbolAddress(&pNode, g_node);
    cudaGetSymbolAddress(&pEdge, g_edge);
    cudaGetSymbolAddress(&pAccO, g_accO);
    cudaGetSymbolAddress(&pWn, g_Wn);
    cudaGetSymbolAddress(&pWe, g_We);
    cudaGetSymbolAddress(&pWo, g_Wo);
    cudaGetSymbolAddress(&pBn, g_bn);
    cudaGetSymbolAddress(&pBe, g_be);
    cudaGetSymbolAddress(&pBo, g_bo);
    cudaGetSymbolAddress(&pDenI, g_denomI);
    cudaGetSymbolAddress(&pDenE, g_denomE);

    cudaFuncSetAttribute(gemm_fp16_t<true>, cudaFuncAttributeMaxDynamicSharedMemorySize, GEMM_SMEM);
    cudaFuncSetAttribute(gemm_fp16_t<false>, cudaFuncAttributeMaxDynamicSharedMemorySize, GEMM_SMEM);

    float* out = (float*)d_out;

    // 1) zero accO (denoms + cnt are zeroed inside pack_weights)
    cudaMemsetAsync(pAccO, 0, (size_t)N * 256 * sizeof(float), 0);

    // 2) pack weights (fp16) / biases (fp32) + zero denoms/cnt
    int packN = 128 * NCC > P ? 128 * NCC : P;
    pack_weights<<<(packN + 255) / 256, 256>>>(Wsi, Wti, Wte, Wmi, Wbi, Wse, Wme, Woi, Woe,
                                               bsi, bti, bbi, bse, bte, bmi, bme, boi, boe,
                                               N, P);

    // 3) projection GEMMs (fp16 MMA) -> combined fp16 tables (biases baked in)
    gemm_fp16_t<true><<<dim3(NCC / 128, N / 128), 256, GEMM_SMEM>>>(
        node_feat, (const __half*)pWn, (const float*)pBn, pNode, 128, NCC, nullptr, nullptr);
    gemm_fp16_t<true><<<dim3(ECC / 128, M / 128), 256, GEMM_SMEM>>>(
        edge_feat, (const __half*)pWe, (const float*)pBe, pEdge, 128, ECC, nullptr, nullptr);

    // 4) CSR build: pair -> bridging edges
    int nbScan = (P + 4095) / 4096;
    csr_hist<<<(T + 255) / 256, 256>>>(tri_pair, T);
    csr_scan_block<<<nbScan, 1024>>>(P);
    csr_scan_partials<<<1, 1024>>>(nbScan);
    csr_add_offsets<<<(P + 255) / 256, 256>>>(P);
    csr_fill<<<(T + 255) / 256, 256>>>(tri_pair, tri_edge, T);

    // 5) merged one-pass attention (softmax via late division)
    int nw = P + E;
    int ab = (int)(((long)nw * 32 + 255) / 256);
    attn_onepass<<<ab, 256>>>(pair_src, pair_tgt, pair_cnt, ai, P,
                              inc_edge, inc_node, ae, E);

    // 6) fused output projection with denominator division folded into A staging:
    //    out = [accI/denI | accE/denE] @ [Woi;Woe] + (boi+boe)
    gemm_fp16_t<false><<<dim3(1, N / 128), 256, GEMM_SMEM>>>(
        (const float*)pAccO, (const __half*)pWo, (const float*)pBo, out, 256, 128,
        (const float*)pDenI, (const float*)pDenE);
}

// round 17
// speedup vs baseline: 1.1647x; 1.1647x over previous
#include <cuda_runtime.h>
#include <cuda_fp16.h>

// ---------------- problem constants ----------------
// N=32768, M=8192, D=128, H=128, NH=2 -> hidden 256, HD=64
#define NMAX 32768
#define MMAX 8192
#define EMAX 49152
#define TMAX 294912
#define PMAX (TMAX + NMAX)

// node table cols: [0:256) S(+bsi+bti+bbi) | [256:512) T | [512:768) T2(+bse+bte) | [768:896) M(+bmi)
#define NCC 896
// edge table cols: [0:256) B | [256:512) S | [512:640) M | [640:768) Me(+bme)
#define ECC 768

// ---------------- scratch ----------------
__device__ __half g_node[(size_t)NMAX * NCC];
__device__ __half g_edge[(size_t)MMAX * ECC];
__device__ float  g_accO[(size_t)NMAX * 256];   // [N][256]: intra 0-127, inter 128-255
__device__ __half g_Wn[128 * NCC];
__device__ __half g_We[128 * ECC];
__device__ __half g_Wo[256 * 128];
__device__ float  g_bn[NCC];
__device__ float  g_be[ECC];
__device__ float  g_bo[128];
__device__ float  g_denomI[NMAX * 2];
__device__ float  g_denomE[NMAX * 2];
// CSR: pair -> bridging edges
__device__ int    g_cnt[PMAX];
__device__ int    g_off[PMAX];
__device__ int    g_head[PMAX];
__device__ int    g_csr[TMAX];
__device__ int    g_partial[1024];

// ---------------- helpers ----------------
__device__ __forceinline__ float rcp_approx(float x) {
    float r;
    asm("rcp.approx.f32 %0, %1;" : "=f"(r) : "f"(x));
    return r;
}
// Branchless exact-gelu via Abramowitz-Stegun 7.1.26 (|erf err| <= 1.5e-7, all z>=0).
__device__ __forceinline__ float gelu_fast(float x) {
    float z = fabsf(x) * 0.70710678118654752f;
    float t = rcp_approx(fmaf(0.3275911f, z, 1.0f));
    float p = 1.061405429f;
    p = fmaf(p, t, -1.453152027f);
    p = fmaf(p, t, 1.421413741f);
    p = fmaf(p, t, -0.284496736f);
    p = fmaf(p, t, 0.254829592f);
    p = p * t;
    float ez = __expf(-z * z);
    float erfz = fmaf(-p, ez, 1.0f);         // erf(|x|/sqrt2) in [0,1)
    float r = copysignf(erfz, x);
    float hx = 0.5f * x;
    return fmaf(hx, r, hx);
}
__device__ __forceinline__ void red4(float* addr, float a, float b, float c, float d) {
    asm volatile("red.global.add.v4.f32 [%0], {%1,%2,%3,%4};"
                 :: "l"(addr), "f"(a), "f"(b), "f"(c), "f"(d) : "memory");
}
__device__ __forceinline__ void load_h8(const __half* p, float* f) {
    uint4 r = *(const uint4*)p;
    float2 v;
    v = __half22float2(*(__half2*)&r.x); f[0] = v.x; f[1] = v.y;
    v = __half22float2(*(__half2*)&r.y); f[2] = v.x; f[3] = v.y;
    v = __half22float2(*(__half2*)&r.z); f[4] = v.x; f[5] = v.y;
    v = __half22float2(*(__half2*)&r.w); f[6] = v.x; f[7] = v.y;
}
__device__ __forceinline__ void load_h4(const __half* p, float* f) {
    uint2 r = *(const uint2*)p;
    float2 v;
    v = __half22float2(*(__half2*)&r.x); f[0] = v.x; f[1] = v.y;
    v = __half22float2(*(__half2*)&r.y); f[2] = v.x; f[3] = v.y;
}

// ---------------- weight/bias packing (weights -> fp16) ----------------
__global__ void pack_weights(const float* __restrict__ Wsi, const float* __restrict__ Wti,
                             const float* __restrict__ Wte, const float* __restrict__ Wmi,
                             const float* __restrict__ Wbi, const float* __restrict__ Wse,
                             const float* __restrict__ Wme,
                             const float* __restrict__ Woi, const float* __restrict__ Woe,
                             const float* __restrict__ bsi, const float* __restrict__ bti,
                             const float* __restrict__ bbi, const float* __restrict__ bse,
                             const float* __restrict__ bte, const float* __restrict__ bmi,
                             const float* __restrict__ bme, const float* __restrict__ boi,
                             const float* __restrict__ boe) {
    int i = blockIdx.x * blockDim.x + threadIdx.x;
    if (i < 128 * NCC) {
        int r = i / NCC, c = i % NCC;
        float v;
        if (c < 256) v = Wsi[r * 256 + c];
        else if (c < 512) v = Wti[r * 256 + (c - 256)];
        else if (c < 768) v = Wte[r * 256 + (c - 512)];
        else v = Wmi[r * 128 + (c - 768)];            // Wmi top half
        g_Wn[i] = __float2half(v);
    }
    if (i < 128 * ECC) {
        int r = i / ECC, c = i % ECC;
        float v;
        if (c < 256) v = Wbi[r * 256 + c];
        else if (c < 512) v = Wse[r * 256 + (c - 256)];
        else if (c < 640) v = Wmi[(128 + r) * 128 + (c - 512)];  // Wmi bottom half
        else v = Wme[r * 128 + (c - 640)];
        g_We[i] = __float2half(v);
    }
    if (i < 256 * 128) {
        int r = i / 128, c = i % 128;
        g_Wo[i] = __float2half((r < 128) ? Woi[r * 128 + c] : Woe[(r - 128) * 128 + c]);
    }
    if (i < NCC) {
        float v;
        if (i < 256) v = bsi[i] + bti[i] + bbi[i];
        else if (i < 512) v = 0.f;
        else if (i < 768) v = bse[i - 512] + bte[i - 512];
        else v = bmi[i - 768];
        g_bn[i] = v;
    }
    if (i < ECC) g_be[i] = (i >= 640) ? bme[i - 640] : 0.f;
    if (i < 128) g_bo[i] = boi[i] + boe[i];
}

// ---------------- fp16 tensor-core GEMM core (macro-expanded body) ----------
// As: [128 rows][68 words] half2 along k. Wp: [64 kk][136 words] k-paired half2.
#define AS_W 68
#define WP_W 136
#define GEMM_SMEM ((128 * AS_W + 64 * WP_W) * 4)

// A-staging scale hook: PLAIN = no scale; DIVI = per-row denominator scale.
#define GEMM_BODY(SCALE_EXPR, STORE_HALF)                                         \
    extern __shared__ unsigned sh[];                                              \
    unsigned* As = sh;                                                            \
    unsigned* Wp = sh + 128 * AS_W;                                               \
    const int tid = threadIdx.x;                                                  \
    const int lane = tid & 31;                                                    \
    const int warp = tid >> 5;                                                    \
    const int wm = warp & 3;                                                      \
    const int wn = warp >> 2;                                                     \
    const long r0 = (long)blockIdx.y * 128;                                       \
    const int  c0 = blockIdx.x * 128;                                             \
    const int gid = lane >> 2;                                                    \
    const int tig = lane & 3;                                                     \
    float c[2][8][4];                                                             \
    for (int mt = 0; mt < 2; mt++)                                                \
        for (int nt = 0; nt < 8; nt++)                                            \
            for (int q = 0; q < 4; q++) c[mt][nt][q] = 0.f;                       \
    for (int kb = 0; kb < KK; kb += 128) {                                        \
        if (kb) __syncthreads();                                                  \
        _Pragma("unroll")                                                         \
        for (int i = 0; i < 16; i++) {                                            \
            int idx = tid + i * 256;                                              \
            int row = idx >> 5;                                                   \
            int c4 = idx & 31;                                                    \
            float4 v = *(const float4*)(A + (r0 + row) * KK + kb + c4 * 4);       \
            SCALE_EXPR;                                                           \
            unsigned w0, w1;                                                      \
            *(__half2*)&w0 = __floats2half2_rn(v.x, v.y);                         \
            *(__half2*)&w1 = __floats2half2_rn(v.z, v.w);                         \
            *(uint2*)(As + row * AS_W + c4 * 2) = make_uint2(w0, w1);             \
        }                                                                         \
        _Pragma("unroll")                                                         \
        for (int i = 0; i < 4; i++) {                                             \
            int idx = tid + i * 256;                                              \
            int kk = idx >> 4;                                                    \
            int cg = idx & 15;                                                    \
            const __half* we = W + (long)(kb + 2 * kk) * CC + c0 + cg * 8;        \
            uint4 e = *(const uint4*)we;                                          \
            uint4 o = *(const uint4*)(we + CC);                                   \
            const unsigned short* eh = (const unsigned short*)&e;                 \
            const unsigned short* oh = (const unsigned short*)&o;                 \
            unsigned outw[8];                                                     \
            _Pragma("unroll")                                                     \
            for (int j = 0; j < 8; j++)                                           \
                outw[j] = (unsigned)eh[j] | ((unsigned)oh[j] << 16);              \
            unsigned* dst = Wp + kk * WP_W + cg * 8;                              \
            *(uint4*)dst = make_uint4(outw[0], outw[1], outw[2], outw[3]);        \
            *(uint4*)(dst + 4) = make_uint4(outw[4], outw[5], outw[6], outw[7]);  \
        }                                                                         \
        __syncthreads();                                                          \
        const int arow = wm * 32 + gid;                                           \
        const int bcol = wn * 64 + gid;                                           \
        _Pragma("unroll")                                                         \
        for (int step = 0; step < 8; step++) {                                    \
            int kw0 = step * 8;                                                   \
            unsigned a[2][4], b[8][2];                                            \
            _Pragma("unroll")                                                     \
            for (int mt = 0; mt < 2; mt++) {                                      \
                const unsigned* ap = As + (arow + mt * 16) * AS_W + kw0 + tig;    \
                a[mt][0] = ap[0];                                                 \
                a[mt][1] = ap[8 * AS_W];                                          \
                a[mt][2] = ap[4];                                                 \
                a[mt][3] = ap[8 * AS_W + 4];                                      \
            }                                                                     \
            _Pragma("unroll")                                                     \
            for (int nt = 0; nt < 8; nt++) {                                      \
                b[nt][0] = Wp[(kw0 + tig) * WP_W + bcol + nt * 8];                \
                b[nt][1] = Wp[(kw0 + tig + 4) * WP_W + bcol + nt * 8];            \
            }                                                                     \
            _Pragma("unroll")                                                     \
            for (int mt = 0; mt < 2; mt++)                                        \
                _Pragma("unroll")                                                 \
                for (int nt = 0; nt < 8; nt++)                                    \
                    asm volatile(                                                 \
                        "mma.sync.aligned.m16n8k16.row.col.f32.f16.f16.f32 "      \
                        "{%0,%1,%2,%3}, {%4,%5,%6,%7}, {%8,%9}, {%0,%1,%2,%3};"   \
                        : "+f"(c[mt][nt][0]), "+f"(c[mt][nt][1]),                 \
                          "+f"(c[mt][nt][2]), "+f"(c[mt][nt][3])                  \
                        : "r"(a[mt][0]), "r"(a[mt][1]), "r"(a[mt][2]),            \
                          "r"(a[mt][3]), "r"(b[nt][0]), "r"(b[nt][1]));           \
        }                                                                         \
    }                                                                             \
    _Pragma("unroll")                                                             \
    for (int mt = 0; mt < 2; mt++) {                                              \
        long r = r0 + wm * 32 + mt * 16 + gid;                                    \
        _Pragma("unroll")                                                         \
        for (int nt = 0; nt < 8; nt++) {                                          \
            int col = c0 + wn * 64 + nt * 8 + 2 * tig;                            \
            float2 bv = bias ? *(const float2*)(bias + col)                       \
                             : make_float2(0.f, 0.f);                             \
            float x0 = c[mt][nt][0] + bv.x, y0 = c[mt][nt][1] + bv.y;             \
            float x1 = c[mt][nt][2] + bv.x, y1 = c[mt][nt][3] + bv.y;             \
            if (STORE_HALF) {                                                     \
                __half* C = (__half*)Cv;                                          \
                *(__half2*)(C + r * CC + col) = __floats2half2_rn(x0, y0);        \
                *(__half2*)(C + (r + 8) * CC + col) = __floats2half2_rn(x1, y1);  \
            } else {                                                              \
                float* C = (float*)Cv;                                            \
                *(float2*)(C + r * CC + col) = make_float2(x0, y0);               \
                *(float2*)(C + (r + 8) * CC + col) = make_float2(x1, y1);         \
            }                                                                     \
        }                                                                         \
    }

#define NO_SCALE
#define DEN_SCALE                                                                 \
    {                                                                             \
        int kblk = (kb + c4 * 4) >> 6;                                            \
        float den = (kblk < 2) ? dI[(r0 + row) * 2 + kblk]                        \
                               : dE[(r0 + row) * 2 + kblk - 2];                   \
        float s = (den > 0.f) ? 1.0f / den : 0.f;                                 \
        v.x *= s; v.y *= s; v.z *= s; v.w *= s;                                   \
    }

// Hot projection GEMM: no scale hook, fp16 output (identical codegen to R12).
__global__ void gemm_fp16(const float* __restrict__ A, const __half* __restrict__ W,
                          const float* __restrict__ bias, void* __restrict__ Cv,
                          int KK, int CC) {
    GEMM_BODY(NO_SCALE, true)
}

// Output GEMM: per-row denominator fold, fp32 output (tiny launch).
__global__ void gemm_fp16_div(const float* __restrict__ A, const __half* __restrict__ W,
                              const float* __restrict__ bias, void* __restrict__ Cv,
                              int KK, int CC,
                              const float* __restrict__ dI, const float* __restrict__ dE) {
    GEMM_BODY(DEN_SCALE, false)
}

// ---------------- CSR build: pair -> bridging edge list ---------------------
__global__ void csr_hist(const int* __restrict__ tri_pair, int T) {
    int i = blockIdx.x * blockDim.x + threadIdx.x;
    if (i < T) atomicAdd(&g_cnt[tri_pair[i]], 1);
}

__global__ void csr_scan_block(int P) {
    __shared__ int wsum[32];
    int tid = threadIdx.x;
    int base = blockIdx.x * 4096 + tid * 4;
    int v[4], s = 0;
#pragma unroll
    for (int q = 0; q < 4; q++) {
        v[q] = (base + q < P) ? g_cnt[base + q] : 0;
        s += v[q];
    }
    int lane = tid & 31, wid = tid >> 5;
    int x = s;
#pragma unroll
    for (int o = 1; o < 32; o <<= 1) {
        int y = __shfl_up_sync(0xffffffffu, x, o);
        if (lane >= o) x += y;
    }
    if (lane == 31) wsum[wid] = x;
    __syncthreads();
    if (wid == 0) {
        int w = wsum[lane];
#pragma unroll
        for (int o = 1; o < 32; o <<= 1) {
            int y = __shfl_up_sync(0xffffffffu, w, o);
            if (lane >= o) w += y;
        }
        wsum[lane] = w;
    }
    __syncthreads();
    int excl = x - s + (wid > 0 ? wsum[wid - 1] : 0);
    int run = excl;
#pragma unroll
    for (int q = 0; q < 4; q++) {
        if (base + q < P) g_off[base + q] = run;
        run += v[q];
    }
    if (tid == 1023) g_partial[blockIdx.x] = wsum[31];
}

__global__ void csr_scan_partials(int nb) {
    __shared__ int wsum[32];
    int tid = threadIdx.x;  // 1024
    int v = (tid < nb) ? g_partial[tid] : 0;
    int lane = tid & 31, wid = tid >> 5;
    int x = v;
#pragma unroll
    for (int o = 1; o < 32; o <<= 1) {
        int y = __shfl_up_sync(0xffffffffu, x, o);
        if (lane >= o) x += y;
    }
    if (lane == 31) wsum[wid] = x;
    __syncthreads();
    if (wid == 0) {
        int w = wsum[lane];
#pragma unroll
        for (int o = 1; o < 32; o <<= 1) {
            int y = __shfl_up_sync(0xffffffffu, w, o);
            if (lane >= o) w += y;
        }
        wsum[lane] = w;
    }
    __syncthreads();
    int excl = x - v + (wid > 0 ? wsum[wid - 1] : 0);
    if (tid < nb) g_partial[tid] = excl;
}

__global__ void csr_add_offsets(int P) {
    int i = blockIdx.x * blockDim.x + threadIdx.x;
    if (i < P) {
        int o = g_off[i] + g_partial[i >> 12];
        g_off[i] = o;
        g_head[i] = o;
    }
}

__global__ void csr_fill(const int* __restrict__ tri_pair,
                         const int* __restrict__ tri_edge, int T) {
    int i = blockIdx.x * blockDim.x + threadIdx.x;
    if (i < T) {
        int pos = atomicAdd(&g_head[tri_pair[i]], 1);
        g_csr[pos] = tri_edge[i];
    }
}

// ---------------- merged one-pass attention (intra + inter) -----------------
// warp id < P  -> intra pair, else inter incidence (id - P).
__global__ void attn_onepass(const int* __restrict__ pair_src, const int* __restrict__ pair_tgt,
                             const float* __restrict__ pair_cnt, const float* __restrict__ ai,
                             int P,
                             const int* __restrict__ inc_edge, const int* __restrict__ inc_node,
                             const float* __restrict__ ae, int E) {
    int w = (int)(((long)blockIdx.x * blockDim.x + threadIdx.x) >> 5);
    int lane = threadIdx.x & 31;

    if (w < P) {
        int s = pair_src[w], t = pair_tgt[w];
        float inv = 1.0f / pair_cnt[w];
        int deg = g_cnt[w];
        int off = g_off[w];

        float u[8], tv[8], m[4];
        load_h8(g_node + (size_t)s * NCC + lane * 8, u);            // S row (+biases)
        load_h8(g_node + (size_t)t * NCC + 256 + lane * 8, tv);     // T row
        load_h4(g_node + (size_t)s * NCC + 768 + lane * 4, m);      // M row (+bmi)
        float ab[8] = {0.f, 0.f, 0.f, 0.f, 0.f, 0.f, 0.f, 0.f};
        float am[4] = {0.f, 0.f, 0.f, 0.f};
        for (int j = 0; j < deg; j++) {
            int e = __ldg(&g_csr[off + j]);
            float bv[8], mv[4];
            load_h8(g_edge + (size_t)e * ECC + lane * 8, bv);       // B row
            load_h4(g_edge + (size_t)e * ECC + 512 + lane * 4, mv); // M row
#pragma unroll
            for (int q = 0; q < 8; q++) ab[q] += bv[q];
#pragma unroll
            for (int q = 0; q < 4; q++) am[q] += mv[q];
        }
        float4 a0 = *(const float4*)(ai + lane * 8);
        float4 a1 = *(const float4*)(ai + lane * 8 + 4);
        float av[8] = {a0.x, a0.y, a0.z, a0.w, a1.x, a1.y, a1.z, a1.w};
        float partial = 0.f;
#pragma unroll
        for (int q = 0; q < 8; q++)
            partial += gelu_fast(u[q] + tv[q] + ab[q] * inv) * av[q];
#pragma unroll
        for (int o = 8; o; o >>= 1) partial += __shfl_down_sync(0xffffffffu, partial, o);
        float l0 = __shfl_sync(0xffffffffu, partial, 0);
        float l1 = __shfl_sync(0xffffffffu, partial, 16);
        float e0 = __expf(l0), e1 = __expf(l1);
        if (lane == 0) {
            atomicAdd(&g_denomI[t * 2], e0);
            atomicAdd(&g_denomI[t * 2 + 1], e1);
        }
        float exh = (lane >> 4) ? e1 : e0;
        red4(g_accO + (size_t)t * 256 + lane * 4,
             exh * (m[0] + am[0] * inv), exh * (m[1] + am[1] * inv),
             exh * (m[2] + am[2] * inv), exh * (m[3] + am[3] * inv));
    } else if (w < P + E) {
        int i = w - P;
        int e = inc_edge[i], n = inc_node[i];
        float u[8], tv[8], m[4];
        load_h8(g_edge + (size_t)e * ECC + 256 + lane * 8, u);      // S(e) row
        load_h8(g_node + (size_t)n * NCC + 512 + lane * 8, tv);     // T2 row (+biases)
        load_h4(g_edge + (size_t)e * ECC + 640 + lane * 4, m);      // Me row (+bme)
        float4 a0 = *(const float4*)(ae + lane * 8);
        float4 a1 = *(const float4*)(ae + lane * 8 + 4);
        float av[8] = {a0.x, a0.y, a0.z, a0.w, a1.x, a1.y, a1.z, a1.w};
        float partial = 0.f;
#pragma unroll
        for (int q = 0; q < 8; q++)
            partial += gelu_fast(u[q] + tv[q]) * av[q];
#pragma unroll
        for (int o = 8; o; o >>= 1) partial += __shfl_down_sync(0xffffffffu, partial, o);
        float l0 = __shfl_sync(0xffffffffu, partial, 0);
        float l1 = __shfl_sync(0xffffffffu, partial, 16);
        float e0 = __expf(l0), e1 = __expf(l1);
        if (lane == 0) {
            atomicAdd(&g_denomE[n * 2], e0);
            atomicAdd(&g_denomE[n * 2 + 1], e1);
        }
        float exh = (lane >> 4) ? e1 : e0;
        red4(g_accO + (size_t)n * 256 + 128 + lane * 4,
             exh * m[0], exh * m[1], exh * m[2], exh * m[3]);
    }
}

// ---------------- launch ----------------
extern "C" void kernel_launch(void* const* d_in, const int* in_sizes, int n_in,
                              void* d_out, int out_size) {
    const float* node_feat = (const float*)d_in[0];
    const float* edge_feat = (const float*)d_in[1];
    const int*   inc_node  = (const int*)d_in[2];
    const int*   inc_edge  = (const int*)d_in[3];
    const int*   pair_src  = (const int*)d_in[4];
    const int*   pair_tgt  = (const int*)d_in[5];
    const float* pair_cnt  = (const float*)d_in[6];
    const int*   tri_pair  = (const int*)d_in[7];
    const int*   tri_edge  = (const int*)d_in[8];
    const float* Wsi = (const float*)d_in[9];
    const float* bsi = (const float*)d_in[10];
    const float* Wti = (const float*)d_in[11];
    const float* bti = (const float*)d_in[12];
    const float* Wbi = (const float*)d_in[13];
    const float* bbi = (const float*)d_in[14];
    const float* ai  = (const float*)d_in[15];
    const float* Wmi = (const float*)d_in[16];
    const float* bmi = (const float*)d_in[17];
    const float* Woi = (const float*)d_in[18];
    const float* boi = (const float*)d_in[19];
    const float* Wse = (const float*)d_in[20];
    const float* bse = (const float*)d_in[21];
    const float* Wte = (const float*)d_in[22];
    const float* bte = (const float*)d_in[23];
    const float* ae  = (const float*)d_in[24];
    const float* Wme = (const float*)d_in[25];
    const float* bme = (const float*)d_in[26];
    const float* Woe = (const float*)d_in[27];
    const float* boe = (const float*)d_in[28];

    const int N = in_sizes[0] / 128;
    const int M = in_sizes[1] / 128;
    const int E = in_sizes[2];
    const int P = in_sizes[4];
    const int T = in_sizes[7];
    if (N > NMAX || M > MMAX || E > EMAX || P > PMAX || T > TMAX) return;

    void *pNode, *pEdge, *pAccO, *pWn, *pWe, *pWo, *pBn, *pBe, *pBo, *pDenI, *pDenE, *pCnt;
    cudaGetSymbolAddress(&pNode, g_node);
    cudaGetSymbolAddress(&pEdge, g_edge);
    cudaGetSymbolAddress(&pAccO, g_accO);
    cudaGetSymbolAddress(&pWn, g_Wn);
    cudaGetSymbolAddress(&pWe, g_We);
    cudaGetSymbolAddress(&pWo, g_Wo);
    cudaGetSymbolAddress(&pBn, g_bn);
    cudaGetSymbolAddress(&pBe, g_be);
    cudaGetSymbolAddress(&pBo, g_bo);
    cudaGetSymbolAddress(&pDenI, g_denomI);
    cudaGetSymbolAddress(&pDenE, g_denomE);
    cudaGetSymbolAddress(&pCnt, g_cnt);

    cudaFuncSetAttribute(gemm_fp16, cudaFuncAttributeMaxDynamicSharedMemorySize, GEMM_SMEM);
    cudaFuncSetAttribute(gemm_fp16_div, cudaFuncAttributeMaxDynamicSharedMemorySize, GEMM_SMEM);

    float* out = (float*)d_out;

    // 1) zero accumulators, denominators, CSR counters (R12-exact)
    cudaMemsetAsync(pAccO, 0, (size_t)N * 256 * sizeof(float), 0);
    cudaMemsetAsync(pDenI, 0, (size_t)N * 2 * sizeof(float), 0);
    cudaMemsetAsync(pDenE, 0, (size_t)N * 2 * sizeof(float), 0);
    cudaMemsetAsync(pCnt, 0, (size_t)P * sizeof(int), 0);

    // 2) pack weights (fp16) / biases (fp32)
    pack_weights<<<(128 * NCC + 255) / 256, 256>>>(Wsi, Wti, Wte, Wmi, Wbi, Wse, Wme, Woi, Woe,
                                                   bsi, bti, bbi, bse, bte, bmi, bme, boi, boe);

    // 3) projection GEMMs (fp16 MMA, plain kernel -> R12-identical codegen)
    gemm_fp16<<<dim3(NCC / 128, N / 128), 256, GEMM_SMEM>>>(
        node_feat, (const __half*)pWn, (const float*)pBn, pNode, 128, NCC);
    gemm_fp16<<<dim3(ECC / 128, M / 128), 256, GEMM_SMEM>>>(
        edge_feat, (const __half*)pWe, (const float*)pBe, pEdge, 128, ECC);

    // 4) CSR build: pair -> bridging edges
    int nbScan = (P + 4095) / 4096;
    csr_hist<<<(T + 255) / 256, 256>>>(tri_pair, T);
    csr_scan_block<<<nbScan, 1024>>>(P);
    csr_scan_partials<<<1, 1024>>>(nbScan);
    csr_add_offsets<<<(P + 255) / 256, 256>>>(P);
    csr_fill<<<(T + 255) / 256, 256>>>(tri_pair, tri_edge, T);

    // 5) merged one-pass attention (softmax via late division)
    int nw = P + E;
    int ab = (int)(((long)nw * 32 + 255) / 256);
    attn_onepass<<<ab, 256>>>(pair_src, pair_tgt, pair_cnt, ai, P,
                              inc_edge, inc_node, ae, E);

    // 6) fused output projection, division folded (separate kernel, tiny launch):
    //    out = [accI/denI | accE/denE] @ [Woi;Woe] + (boi+boe)
    gemm_fp16_div<<<dim3(1, N / 128), 256, GEMM_SMEM>>>(
        (const float*)pAccO, (const __half*)pWo, (const float*)pBo, out, 256, 128,
        (const float*)pDenI, (const float*)pDenE);
}